// round 1
// baseline (speedup 1.0000x reference)
#include <cuda_runtime.h>
#include <cuda_bf16.h>
#include <cstdint>
#include <cstddef>

#define DEV_INLINE __device__ __forceinline__

// ---------------------------------------------------------------------------
// Problem constants
// ---------------------------------------------------------------------------
static constexpr int H  = 1024;
static constexpr int E  = 2048;
static constexpr int NS = 16;     // state dim
static constexpr int RK = 64;     // dt_rank
static constexpr int BSZ = 4;
static constexpr int SEQ = 2048;
static constexpr int ROWS = BSZ * SEQ;          // 8192 tokens
static constexpr int CATN = 128;                // 64 (dr) + 16 (B) + 16 (C) + pad

// ---------------------------------------------------------------------------
// Scratch (device globals: allocation-free rule)
// ---------------------------------------------------------------------------
__device__ float g_xn  [(size_t)ROWS * H];        // 32 MB  layernorm out
__device__ float g_act [(size_t)ROWS * 2 * E];    // 128 MB silu(u) | silu(gate)
__device__ float g_dbc [(size_t)ROWS * CATN];     // 4 MB   dr(64) | Bm(16) | Cm(16)
__device__ float g_delta[(size_t)ROWS * E];       // 64 MB  softplus delta
__device__ float g_yv  [(size_t)ROWS * E];        // 64 MB  scan output * gate
__device__ float g_A2  [E * NS];                  // -exp(A_log) * log2(e)
__device__ float g_wcat[(size_t)E * CATN];        // concat W_delta|W_B|W_C|0
__device__ float g_bcat[CATN];

// ---------------------------------------------------------------------------
// Helpers
// ---------------------------------------------------------------------------
DEV_INLINE unsigned f2tf(float f) {
    unsigned r; asm("cvt.rna.tf32.f32 %0, %1;" : "=r"(r) : "f"(f)); return r;
}
DEV_INLINE float ex2f(float x) {
    float y; asm("ex2.approx.ftz.f32 %0, %1;" : "=f"(y) : "f"(x)); return y;
}
DEV_INLINE float siluf(float v)     { return v / (1.f + __expf(-v)); }
DEV_INLINE float softplusf(float v) { return v > 20.f ? v : log1pf(__expf(v)); }

DEV_INLINE void mma_tf32(float c[4], const unsigned a[4], const unsigned b[2]) {
    asm volatile(
        "mma.sync.aligned.m16n8k8.row.col.f32.tf32.tf32.f32 "
        "{%0,%1,%2,%3}, {%4,%5,%6,%7}, {%8,%9}, {%0,%1,%2,%3};\n"
        : "+f"(c[0]), "+f"(c[1]), "+f"(c[2]), "+f"(c[3])
        : "r"(a[0]), "r"(a[1]), "r"(a[2]), "r"(a[3]), "r"(b[0]), "r"(b[1]));
}

// ---------------------------------------------------------------------------
// Prep: A2 = -exp(A_log) * log2(e);  concat weights/biases for fused proj GEMM
// ---------------------------------------------------------------------------
__global__ void prep_kernel(const float* __restrict__ A_log,
                            const float* __restrict__ W_delta,
                            const float* __restrict__ W_B,
                            const float* __restrict__ W_C,
                            const float* __restrict__ b_delta,
                            const float* __restrict__ b_B,
                            const float* __restrict__ b_C) {
    int i = blockIdx.x * blockDim.x + threadIdx.x;
    if (i < E * NS) g_A2[i] = -__expf(A_log[i]) * 1.4426950408889634f;
    if (i < E * CATN) {
        int k = i >> 7, j = i & 127;
        float v = 0.f;
        if (j < 64)      v = W_delta[k * 64 + j];
        else if (j < 80) v = W_B[k * 16 + (j - 64)];
        else if (j < 96) v = W_C[k * 16 + (j - 80)];
        g_wcat[i] = v;
    }
    if (i < CATN) {
        float v = 0.f;
        if (i < 64)      v = b_delta[i];
        else if (i < 80) v = b_B[i - 64];
        else if (i < 96) v = b_C[i - 80];
        g_bcat[i] = v;
    }
}

// ---------------------------------------------------------------------------
// LayerNorm: one CTA (256 thr) per row of 1024
// ---------------------------------------------------------------------------
__global__ __launch_bounds__(256) void ln_kernel(const float* __restrict__ x,
                                                 const float* __restrict__ g,
                                                 const float* __restrict__ b) {
    int row = blockIdx.x, tid = threadIdx.x;
    float4 v = ((const float4*)(x + (size_t)row * H))[tid];
    float s  = v.x + v.y + v.z + v.w;
    float ss = v.x * v.x + v.y * v.y + v.z * v.z + v.w * v.w;
#pragma unroll
    for (int o = 16; o; o >>= 1) {
        s  += __shfl_xor_sync(0xffffffffu, s, o);
        ss += __shfl_xor_sync(0xffffffffu, ss, o);
    }
    __shared__ float rs[8], rss[8];
    if ((tid & 31) == 0) { rs[tid >> 5] = s; rss[tid >> 5] = ss; }
    __syncthreads();
    s = 0.f; ss = 0.f;
#pragma unroll
    for (int i = 0; i < 8; i++) { s += rs[i]; ss += rss[i]; }
    float mean = s * (1.f / H);
    float var  = ss * (1.f / H) - mean * mean;
    float rstd = rsqrtf(var + 1e-5f);
    float4 gg = ((const float4*)g)[tid];
    float4 bb = ((const float4*)b)[tid];
    float4 o;
    o.x = (v.x - mean) * rstd * gg.x + bb.x;
    o.y = (v.y - mean) * rstd * gg.y + bb.y;
    o.z = (v.z - mean) * rstd * gg.z + bb.z;
    o.w = (v.w - mean) * rstd * gg.w + bb.w;
    ((float4*)(g_xn + (size_t)row * H))[tid] = o;
}

// ---------------------------------------------------------------------------
// TF32 mma.sync GEMM: C[M,N] = epi(A[M,K] @ B[K,N] + bias)
//   A row-major (lda), B row-major (ldb), C row-major (ldc)
//   EPI: 0 none, 1 silu, 2 softplus, 3 +extra (residual)
// ---------------------------------------------------------------------------
template <int BM, int BN, int BK, int WM, int WN, int EPI>
__global__ void __launch_bounds__((BM / WM) * (BN / WN) * 32)
gemm_tf32(const float* __restrict__ A, const float* __restrict__ B,
          const float* __restrict__ bias, const float* __restrict__ extra,
          float* __restrict__ C, int M, int N, int K,
          int lda, int ldb, int ldc) {
    constexpr int WARPS_M = BM / WM, WARPS_N = BN / WN;
    constexpr int NT  = WARPS_M * WARPS_N * 32;
    constexpr int MT  = WM / 16;
    constexpr int NTL = WN / 8;
    constexpr int KK  = BK / 8;
    constexpr int AV  = BM * BK / 4 / NT;   // float4 per thread (A tile)
    constexpr int ARP = NT / (BK / 4);
    constexpr int BV  = BK * BN / 4 / NT;
    constexpr int BRP = NT / (BN / 4);

    __shared__ unsigned As[BM][BK + 4];
    __shared__ unsigned Bs[BK][BN + 8];

    int tid = threadIdx.x;
    int wid = tid >> 5, lane = tid & 31;
    int wm = wid / WARPS_N, wn = wid % WARPS_N;
    int bm = blockIdx.y, bn = blockIdx.x;

    int a_r = tid / (BK / 4), a_c = (tid % (BK / 4)) * 4;
    int b_r = tid / (BN / 4), b_c = (tid % (BN / 4)) * 4;

    const float* Ag = A + (size_t)(bm * BM + a_r) * lda + a_c;
    const float* Bg = B + (size_t)b_r * ldb + bn * BN + b_c;

    float4 afr[AV], bfr[BV];
#pragma unroll
    for (int i = 0; i < AV; i++) afr[i] = *(const float4*)(Ag + (size_t)i * ARP * lda);
#pragma unroll
    for (int i = 0; i < BV; i++) bfr[i] = *(const float4*)(Bg + (size_t)i * BRP * ldb);

    float acc[MT][NTL][4];
#pragma unroll
    for (int mi = 0; mi < MT; mi++)
#pragma unroll
        for (int ni = 0; ni < NTL; ni++)
#pragma unroll
            for (int j = 0; j < 4; j++) acc[mi][ni][j] = 0.f;

    int ktiles = K / BK;
    for (int kt = 0; kt < ktiles; kt++) {
        // regs -> smem (tf32)
#pragma unroll
        for (int i = 0; i < AV; i++) {
            unsigned* p = &As[a_r + i * ARP][a_c];
            p[0] = f2tf(afr[i].x); p[1] = f2tf(afr[i].y);
            p[2] = f2tf(afr[i].z); p[3] = f2tf(afr[i].w);
        }
#pragma unroll
        for (int i = 0; i < BV; i++) {
            unsigned* p = &Bs[b_r + i * BRP][b_c];
            p[0] = f2tf(bfr[i].x); p[1] = f2tf(bfr[i].y);
            p[2] = f2tf(bfr[i].z); p[3] = f2tf(bfr[i].w);
        }
        __syncthreads();

        if (kt + 1 < ktiles) {   // prefetch next tile into regs
            const float* Ag2 = Ag + (size_t)(kt + 1) * BK;
            const float* Bg2 = Bg + (size_t)(kt + 1) * BK * ldb;
#pragma unroll
            for (int i = 0; i < AV; i++) afr[i] = *(const float4*)(Ag2 + (size_t)i * ARP * lda);
#pragma unroll
            for (int i = 0; i < BV; i++) bfr[i] = *(const float4*)(Bg2 + (size_t)i * BRP * ldb);
        }

#pragma unroll
        for (int kk = 0; kk < KK; kk++) {
            unsigned af[MT][4], bf[NTL][2];
#pragma unroll
            for (int mi = 0; mi < MT; mi++) {
                int r = wm * WM + mi * 16 + (lane >> 2);
                int kc = kk * 8 + (lane & 3);
                af[mi][0] = As[r][kc];
                af[mi][1] = As[r + 8][kc];
                af[mi][2] = As[r][kc + 4];
                af[mi][3] = As[r + 8][kc + 4];
            }
#pragma unroll
            for (int ni = 0; ni < NTL; ni++) {
                int cl = wn * WN + ni * 8 + (lane >> 2);
                int kr = kk * 8 + (lane & 3);
                bf[ni][0] = Bs[kr][cl];
                bf[ni][1] = Bs[kr + 4][cl];
            }
#pragma unroll
            for (int mi = 0; mi < MT; mi++)
#pragma unroll
                for (int ni = 0; ni < NTL; ni++)
                    mma_tf32(acc[mi][ni], af[mi], bf[ni]);
        }
        __syncthreads();
    }

    // epilogue
#pragma unroll
    for (int mi = 0; mi < MT; mi++) {
#pragma unroll
        for (int ni = 0; ni < NTL; ni++) {
            int r  = bm * BM + wm * WM + mi * 16 + (lane >> 2);
            int c0 = bn * BN + wn * WN + ni * 8 + (lane & 3) * 2;
            float b0 = bias[c0], b1 = bias[c0 + 1];
            float v0 = acc[mi][ni][0] + b0;
            float v1 = acc[mi][ni][1] + b1;
            float v2 = acc[mi][ni][2] + b0;
            float v3 = acc[mi][ni][3] + b1;
            if (EPI == 1) { v0 = siluf(v0); v1 = siluf(v1); v2 = siluf(v2); v3 = siluf(v3); }
            else if (EPI == 2) { v0 = softplusf(v0); v1 = softplusf(v1); v2 = softplusf(v2); v3 = softplusf(v3); }
            else if (EPI == 3) {
                v0 += extra[(size_t)r * ldc + c0];
                v1 += extra[(size_t)r * ldc + c0 + 1];
                v2 += extra[(size_t)(r + 8) * ldc + c0];
                v3 += extra[(size_t)(r + 8) * ldc + c0 + 1];
            }
            float2 p0 = make_float2(v0, v1), p1 = make_float2(v2, v3);
            *(float2*)&C[(size_t)r * ldc + c0] = p0;
            *(float2*)&C[(size_t)(r + 8) * ldc + c0] = p1;
        }
    }
}

// ---------------------------------------------------------------------------
// Selective scan, fused with D-term and silu(gate) multiply.
// CTA: 64 channels x 4 threads (4 states each). grid = (E/64, BSZ).
// ---------------------------------------------------------------------------
static constexpr int SCE = 64;   // channels / CTA
static constexpr int STC = 32;   // time chunk

__global__ __launch_bounds__(256) void scan_kernel(const float* __restrict__ D) {
    __shared__ float s_d[STC][SCE];
    __shared__ float s_u[STC][SCE];
    __shared__ float s_g[STC][SCE];
    __shared__ float s_y[STC][SCE];
    __shared__ float s_bc[STC][32];

    int b  = blockIdx.y;
    int e0 = blockIdx.x * SCE;
    int tid = threadIdx.x;
    int c = tid >> 2;        // channel in block
    int q = tid & 3;         // state quarter
    int e = e0 + c;

    float4 a2 = *(const float4*)&g_A2[e * NS + q * 4];
    float dterm = D[e];
    float h0 = 0.f, h1 = 0.f, h2 = 0.f, h3 = 0.f;

    for (int t0 = 0; t0 < SEQ; t0 += STC) {
        // stage inputs
        for (int i = tid; i < STC * SCE; i += 256) {
            int tt = i / SCE, ee = i % SCE;
            size_t row = (size_t)(b * SEQ + t0 + tt);
            s_d[tt][ee] = g_delta[row * E + e0 + ee];
            s_u[tt][ee] = g_act[row * (2 * E) + e0 + ee];
            s_g[tt][ee] = g_act[row * (2 * E) + E + e0 + ee];
        }
        for (int i = tid; i < STC * 32; i += 256) {
            int tt = i >> 5, nn = i & 31;
            s_bc[tt][nn] = g_dbc[(size_t)(b * SEQ + t0 + tt) * CATN + 64 + nn];
        }
        __syncthreads();

#pragma unroll 4
        for (int tt = 0; tt < STC; tt++) {
            float d  = s_d[tt][c];
            float uv = s_u[tt][c];
            float du = d * uv;
            float4 bb = *(const float4*)&s_bc[tt][q * 4];
            float4 cc = *(const float4*)&s_bc[tt][16 + q * 4];
            float a0 = ex2f(d * a2.x);
            float a1 = ex2f(d * a2.y);
            float a2v = ex2f(d * a2.z);
            float a3 = ex2f(d * a2.w);
            h0 = fmaf(a0, h0, du * bb.x);
            h1 = fmaf(a1, h1, du * bb.y);
            h2 = fmaf(a2v, h2, du * bb.z);
            h3 = fmaf(a3, h3, du * bb.w);
            float yp = cc.x * h0 + cc.y * h1 + cc.z * h2 + cc.w * h3;
            yp += __shfl_xor_sync(0xffffffffu, yp, 1);
            yp += __shfl_xor_sync(0xffffffffu, yp, 2);
            if (q == 0) s_y[tt][c] = (yp + uv * dterm) * s_g[tt][c];
        }
        __syncthreads();

        // coalesced store
        for (int i = tid; i < STC * SCE; i += 256) {
            int tt = i / SCE, ee = i % SCE;
            g_yv[(size_t)(b * SEQ + t0 + tt) * E + e0 + ee] = s_y[tt][ee];
        }
        __syncthreads();
    }
}

// ---------------------------------------------------------------------------
// Launch
// ---------------------------------------------------------------------------
extern "C" void kernel_launch(void* const* d_in, const int* in_sizes, int n_in,
                              void* d_out, int out_size) {
    const float* x       = (const float*)d_in[0];
    const float* ln_g    = (const float*)d_in[1];
    const float* ln_b    = (const float*)d_in[2];
    const float* W_in    = (const float*)d_in[3];
    const float* b_in    = (const float*)d_in[4];
    const float* W_delta = (const float*)d_in[5];
    const float* b_delta = (const float*)d_in[6];
    const float* W_dt    = (const float*)d_in[7];
    const float* b_dt    = (const float*)d_in[8];
    const float* W_B     = (const float*)d_in[9];
    const float* b_B     = (const float*)d_in[10];
    const float* W_C     = (const float*)d_in[11];
    const float* b_C     = (const float*)d_in[12];
    const float* A_log   = (const float*)d_in[13];
    const float* Dp      = (const float*)d_in[14];
    const float* W_out   = (const float*)d_in[15];
    const float* b_out   = (const float*)d_in[16];
    float* out = (float*)d_out;

    float *p_xn, *p_act, *p_dbc, *p_delta, *p_yv, *p_wcat, *p_bcat;
    cudaGetSymbolAddress((void**)&p_xn,   g_xn);
    cudaGetSymbolAddress((void**)&p_act,  g_act);
    cudaGetSymbolAddress((void**)&p_dbc,  g_dbc);
    cudaGetSymbolAddress((void**)&p_delta,g_delta);
    cudaGetSymbolAddress((void**)&p_yv,   g_yv);
    cudaGetSymbolAddress((void**)&p_wcat, g_wcat);
    cudaGetSymbolAddress((void**)&p_bcat, g_bcat);

    // 1. prep (A2 + weight concat)
    prep_kernel<<<(E * CATN + 255) / 256, 256>>>(A_log, W_delta, W_B, W_C,
                                                 b_delta, b_B, b_C);
    // 2. layernorm
    ln_kernel<<<ROWS, 256>>>(x, ln_g, ln_b);

    // 3. in-proj + silu: act[8192, 4096] = silu(xn @ W_in + b_in)
    gemm_tf32<128, 128, 32, 64, 32, 1><<<dim3(2 * E / 128, ROWS / 128), 256>>>(
        p_xn, W_in, b_in, nullptr, p_act, ROWS, 2 * E, H, H, 2 * E, 2 * E);

    // 4. fused dr|B|C projection: dbc[8192, 128] = u @ wcat + bcat
    gemm_tf32<64, 128, 32, 32, 64, 0><<<dim3(1, ROWS / 64), 128>>>(
        p_act, p_wcat, p_bcat, nullptr, p_dbc, ROWS, CATN, E, 2 * E, CATN, CATN);

    // 5. delta: softplus(dr @ W_dt + b_dt)  [8192, 2048]
    gemm_tf32<128, 128, 32, 64, 32, 2><<<dim3(E / 128, ROWS / 128), 256>>>(
        p_dbc, W_dt, b_dt, nullptr, p_delta, ROWS, E, RK, CATN, E, E);

    // 6. selective scan (fused D-term + gate)
    scan_kernel<<<dim3(E / SCE, BSZ), 256>>>(Dp);

    // 7. out-proj + bias + residual
    gemm_tf32<128, 128, 32, 64, 32, 3><<<dim3(H / 128, ROWS / 128), 256>>>(
        p_yv, W_out, b_out, x, out, ROWS, H, E, E, H, H);
}

// round 3
// speedup vs baseline: 1.7119x; 1.7119x over previous
#include <cuda_runtime.h>
#include <cuda_fp16.h>
#include <cstdint>
#include <cstddef>

#define DEV_INLINE __device__ __forceinline__

// ---------------------------------------------------------------------------
// Problem constants
// ---------------------------------------------------------------------------
static constexpr int H  = 1024;
static constexpr int E  = 2048;
static constexpr int NS = 16;     // state dim
static constexpr int RK = 64;     // dt_rank
static constexpr int BSZ = 4;
static constexpr int SEQ = 2048;
static constexpr int ROWS = BSZ * SEQ;          // 8192 tokens
static constexpr int CATN = 128;                // 64 (dr) + 16 (B) + 16 (C) + pad

// ---------------------------------------------------------------------------
// Scratch (device globals: allocation-free rule)
// ---------------------------------------------------------------------------
__device__ __half g_xn_h [(size_t)ROWS * H];          // 16 MB  LN out (fp16)
__device__ float  g_act  [(size_t)ROWS * 2 * E];      // 128 MB silu(u)|silu(gate) fp32
__device__ __half g_u_h  [(size_t)ROWS * E];          // 32 MB  silu(u) fp16
__device__ float  g_dbc_part[4 * (size_t)ROWS * CATN];// 16 MB  split-K partials
__device__ float  g_dbc  [(size_t)ROWS * CATN];       // 4 MB   dr|B|C fp32
__device__ __half g_dr_h [(size_t)ROWS * RK];         // 1 MB   dr fp16
__device__ float  g_delta[(size_t)ROWS * E];          // 64 MB  softplus delta
__device__ __half g_yv_h [(size_t)ROWS * E];          // 32 MB  scan out * gate fp16
__device__ float  g_A2   [E * NS];                    // -exp(A_log)*log2(e)
__device__ float  g_bcat [CATN];
__device__ __half g_wti_h [(size_t)(2 * E) * H];      // W_in^T  [4096][1024] fp16
__device__ __half g_wcat_h[(size_t)CATN * E];         // Wcat^T  [128][2048]  fp16
__device__ __half g_wdt_h [(size_t)E * RK];           // W_dt^T  [2048][64]   fp16
__device__ __half g_wto_h [(size_t)H * E];            // W_out^T [1024][2048] fp16

// ---------------------------------------------------------------------------
// Helpers
// ---------------------------------------------------------------------------
DEV_INLINE uint32_t smem_u32(const void* p) {
    uint32_t a;
    asm("{ .reg .u64 t; cvta.to.shared.u64 t, %1; cvt.u32.u64 %0, t; }"
        : "=r"(a) : "l"(p));
    return a;
}
DEV_INLINE uint32_t sw64(uint32_t off) { return off ^ ((off >> 3) & 0x70); }

DEV_INLINE void cp16(uint32_t dst, const void* src) {
    asm volatile("cp.async.cg.shared.global [%0], [%1], 16;" :: "r"(dst), "l"(src));
}
DEV_INLINE void ldsm4(uint32_t& r0, uint32_t& r1, uint32_t& r2, uint32_t& r3,
                      uint32_t a) {
    asm volatile("ldmatrix.sync.aligned.m8n8.x4.shared.b16 {%0,%1,%2,%3}, [%4];"
                 : "=r"(r0), "=r"(r1), "=r"(r2), "=r"(r3) : "r"(a));
}
DEV_INLINE void mma16816(float c[4], const uint32_t a[4], const uint32_t b[2]) {
    asm volatile(
        "mma.sync.aligned.m16n8k16.row.col.f32.f16.f16.f32 "
        "{%0,%1,%2,%3}, {%4,%5,%6,%7}, {%8,%9}, {%0,%1,%2,%3};"
        : "+f"(c[0]), "+f"(c[1]), "+f"(c[2]), "+f"(c[3])
        : "r"(a[0]), "r"(a[1]), "r"(a[2]), "r"(a[3]), "r"(b[0]), "r"(b[1]));
}

DEV_INLINE float ex2f(float x) {
    float y; asm("ex2.approx.ftz.f32 %0, %1;" : "=f"(y) : "f"(x)); return y;
}
DEV_INLINE float siluf(float v)     { return v / (1.f + __expf(-v)); }
DEV_INLINE float softplusf(float v) { return v > 20.f ? v : log1pf(__expf(v)); }

// ---------------------------------------------------------------------------
// Prep kernels
// ---------------------------------------------------------------------------
__global__ void prep_small(const float* __restrict__ A_log,
                           const float* __restrict__ b_delta,
                           const float* __restrict__ b_B,
                           const float* __restrict__ b_C) {
    int i = blockIdx.x * blockDim.x + threadIdx.x;
    if (i < E * NS) g_A2[i] = -__expf(A_log[i]) * 1.4426950408889634f;
    if (i < CATN) {
        float v = 0.f;
        if (i < 64)      v = b_delta[i];
        else if (i < 80) v = b_B[i - 64];
        else if (i < 96) v = b_C[i - 80];
        g_bcat[i] = v;
    }
}

// Wcat^T [128][2048] fp16 directly from W_delta/W_B/W_C
__global__ void wcat_kernel(const float* __restrict__ W_delta,
                            const float* __restrict__ W_B,
                            const float* __restrict__ W_C) {
    int i = blockIdx.x * blockDim.x + threadIdx.x;   // over CATN*E
    int n = i >> 11, k = i & 2047;
    float v = 0.f;
    if (n < 64)      v = W_delta[k * 64 + n];
    else if (n < 80) v = W_B[k * 16 + (n - 64)];
    else if (n < 96) v = W_C[k * 16 + (n - 80)];
    g_wcat_h[i] = __float2half(v);
}

// transpose + convert: in fp32 [R][C] -> out fp16 [C][R]
__global__ void trc_kernel(const float* __restrict__ in, __half* __restrict__ out,
                           int R, int C) {
    __shared__ float t[32][33];
    int bx = blockIdx.x * 32, by = blockIdx.y * 32;   // bx over C, by over R
    int x = bx + threadIdx.x;
#pragma unroll
    for (int i = 0; i < 32; i += 8)
        t[threadIdx.y + i][threadIdx.x] = in[(size_t)(by + threadIdx.y + i) * C + x];
    __syncthreads();
    int ox = by + threadIdx.x;
#pragma unroll
    for (int i = 0; i < 32; i += 8)
        out[(size_t)(bx + threadIdx.y + i) * R + ox] =
            __float2half(t[threadIdx.x][threadIdx.y + i]);
}

// ---------------------------------------------------------------------------
// LayerNorm -> fp16
// ---------------------------------------------------------------------------
__global__ __launch_bounds__(256) void ln_kernel(const float* __restrict__ x,
                                                 const float* __restrict__ g,
                                                 const float* __restrict__ b) {
    int row = blockIdx.x, tid = threadIdx.x;
    float4 v = ((const float4*)(x + (size_t)row * H))[tid];
    float s  = v.x + v.y + v.z + v.w;
    float ss = v.x * v.x + v.y * v.y + v.z * v.z + v.w * v.w;
#pragma unroll
    for (int o = 16; o; o >>= 1) {
        s  += __shfl_xor_sync(0xffffffffu, s, o);
        ss += __shfl_xor_sync(0xffffffffu, ss, o);
    }
    __shared__ float rs[8], rss[8];
    if ((tid & 31) == 0) { rs[tid >> 5] = s; rss[tid >> 5] = ss; }
    __syncthreads();
    s = 0.f; ss = 0.f;
#pragma unroll
    for (int i = 0; i < 8; i++) { s += rs[i]; ss += rss[i]; }
    float mean = s * (1.f / H);
    float var  = ss * (1.f / H) - mean * mean;
    float rstd = rsqrtf(var + 1e-5f);
    float4 gg = ((const float4*)g)[tid];
    float4 bb = ((const float4*)b)[tid];
    float o0 = (v.x - mean) * rstd * gg.x + bb.x;
    float o1 = (v.y - mean) * rstd * gg.y + bb.y;
    float o2 = (v.z - mean) * rstd * gg.z + bb.z;
    float o3 = (v.w - mean) * rstd * gg.w + bb.w;
    __half* op = g_xn_h + (size_t)row * H + 4 * tid;
    *(__half2*)(op)     = __floats2half2_rn(o0, o1);
    *(__half2*)(op + 2) = __floats2half2_rn(o2, o3);
}

// ---------------------------------------------------------------------------
// fp16 mma.sync GEMM, 128x128x32 tiles, 3-stage cp.async, ldmatrix.
// C[M,N] = epi(A[M,K] @ Bt[N,K]^T + bias)
//   A fp16 row-major (lda), Bt fp16 [N][K] row-major (ldb), C fp32 (ldc)
// EPI: 0 raw (split-K partial), 1 silu + dual fp16 write, 2 softplus, 3 +extra
// ---------------------------------------------------------------------------
template <int EPI>
__global__ void __launch_bounds__(256, 2)
gemm_f16(const __half* __restrict__ A, const __half* __restrict__ Bt,
         const float* __restrict__ bias, const float* __restrict__ extra,
         float* __restrict__ C, __half* __restrict__ C2,
         int K, int lda, int ldb, int ldc, size_t partStride) {
    __shared__ char smem[49152];          // 3 stages x (8KB A + 8KB B)
    uint32_t sb = smem_u32(smem);

    int tid = threadIdx.x, wid = tid >> 5, lane = tid & 31;
    int wm = wid >> 2, wn = wid & 3;       // 2 x 4 warps
    int bm = blockIdx.y, bn = blockIdx.x;
    int kbase = blockIdx.z * K;
    C += (size_t)blockIdx.z * partStride;

    // loader: thread -> rows {lr, lr+64}, 16B chunk lc
    int lr = tid >> 2, lc = tid & 3;
    const __half* Ag = A + (size_t)(bm * 128 + lr) * lda + kbase + lc * 8;
    const __half* Bg = Bt + (size_t)(bn * 128 + lr) * ldb + kbase + lc * 8;
    uint32_t swl0 = sw64((uint32_t)lr * 64 + lc * 16);
    uint32_t swl1 = sw64((uint32_t)(lr + 64) * 64 + lc * 16);

    int nkt = K / 32;
#define ISSUE(kt, s) do {                                                     \
        const __half* Ak = Ag + (kt) * 32;                                    \
        const __half* Bk = Bg + (kt) * 32;                                    \
        uint32_t base = sb + (s) * 16384;                                     \
        cp16(base + swl0, Ak);                                                \
        cp16(base + swl1, Ak + (size_t)64 * lda);                             \
        cp16(base + 8192 + swl0, Bk);                                         \
        cp16(base + 8192 + swl1, Bk + (size_t)64 * ldb);                      \
    } while (0)

    if (0 < nkt) ISSUE(0, 0);
    asm volatile("cp.async.commit_group;" ::: "memory");
    if (1 < nkt) ISSUE(1, 1);
    asm volatile("cp.async.commit_group;" ::: "memory");

    float acc[4][4][4];
#pragma unroll
    for (int mi = 0; mi < 4; mi++)
#pragma unroll
        for (int ni = 0; ni < 4; ni++)
#pragma unroll
            for (int j = 0; j < 4; j++) acc[mi][ni][j] = 0.f;

    int within = lane & 7, mat = lane >> 3;

    for (int kt = 0; kt < nkt; kt++) {
        asm volatile("cp.async.wait_group 1;" ::: "memory");
        __syncthreads();
        int pre = kt + 2;
        if (pre < nkt) ISSUE(pre, pre % 3);
        asm volatile("cp.async.commit_group;" ::: "memory");

        uint32_t sA = sb + (kt % 3) * 16384;
        uint32_t sB = sA + 8192;
#pragma unroll
        for (int kk = 0; kk < 2; kk++) {
            uint32_t af[4][4], bf[4][2];
#pragma unroll
            for (int mi = 0; mi < 4; mi++) {
                int ra = wm * 64 + mi * 16;
                int row = ra + within + ((mat & 1) << 3);
                int ch  = 2 * kk + (mat >> 1);
                uint32_t ad = sA + sw64((uint32_t)row * 64 + ch * 16);
                ldsm4(af[mi][0], af[mi][1], af[mi][2], af[mi][3], ad);
            }
#pragma unroll
            for (int np = 0; np < 2; np++) {
                int nb = wn * 32 + np * 16;
                int n  = nb + within + ((mat >> 1) << 3);
                int ch = 2 * kk + (mat & 1);
                uint32_t bd = sB + sw64((uint32_t)n * 64 + ch * 16);
                uint32_t r0, r1, r2, r3;
                ldsm4(r0, r1, r2, r3, bd);
                bf[2 * np][0] = r0; bf[2 * np][1] = r1;
                bf[2 * np + 1][0] = r2; bf[2 * np + 1][1] = r3;
            }
#pragma unroll
            for (int mi = 0; mi < 4; mi++)
#pragma unroll
                for (int ni = 0; ni < 4; ni++)
                    mma16816(acc[mi][ni], af[mi], bf[ni]);
        }
        __syncthreads();
    }
#undef ISSUE

    // epilogue
#pragma unroll
    for (int mi = 0; mi < 4; mi++) {
#pragma unroll
        for (int ni = 0; ni < 4; ni++) {
            int r  = bm * 128 + wm * 64 + mi * 16 + (lane >> 2);
            int c0 = bn * 128 + wn * 32 + ni * 8 + (lane & 3) * 2;
            float v0 = acc[mi][ni][0], v1 = acc[mi][ni][1];
            float v2 = acc[mi][ni][2], v3 = acc[mi][ni][3];
            if (EPI != 0) {
                float b0 = bias[c0], b1 = bias[c0 + 1];
                v0 += b0; v1 += b1; v2 += b0; v3 += b1;
            }
            if (EPI == 1) {
                v0 = siluf(v0); v1 = siluf(v1); v2 = siluf(v2); v3 = siluf(v3);
            } else if (EPI == 2) {
                v0 = softplusf(v0); v1 = softplusf(v1);
                v2 = softplusf(v2); v3 = softplusf(v3);
            } else if (EPI == 3) {
                v0 += extra[(size_t)r * ldc + c0];
                v1 += extra[(size_t)r * ldc + c0 + 1];
                v2 += extra[(size_t)(r + 8) * ldc + c0];
                v3 += extra[(size_t)(r + 8) * ldc + c0 + 1];
            }
            *(float2*)&C[(size_t)r * ldc + c0]       = make_float2(v0, v1);
            *(float2*)&C[(size_t)(r + 8) * ldc + c0] = make_float2(v2, v3);
            if (EPI == 1 && c0 < E) {
                *(__half2*)&C2[(size_t)r * E + c0]       = __floats2half2_rn(v0, v1);
                *(__half2*)&C2[(size_t)(r + 8) * E + c0] = __floats2half2_rn(v2, v3);
            }
        }
    }
}

// ---------------------------------------------------------------------------
// Reduce split-K partials + bias -> dbc fp32, dr fp16
// ---------------------------------------------------------------------------
__global__ void reduce_dbc() {
    int i = blockIdx.x * blockDim.x + threadIdx.x;   // over ROWS*CATN/4
    int row = i >> 5, j4 = i & 31;
    size_t off = (size_t)row * CATN + j4 * 4;
    const float4* p0 = (const float4*)&g_dbc_part[off];
    size_t stride4 = (size_t)ROWS * CATN / 4;
    float4 a = ((const float4*)g_dbc_part)[off / 4];
    float4 b = ((const float4*)g_dbc_part)[off / 4 + stride4];
    float4 c = ((const float4*)g_dbc_part)[off / 4 + 2 * stride4];
    float4 d = ((const float4*)g_dbc_part)[off / 4 + 3 * stride4];
    float4 bias = *(const float4*)&g_bcat[j4 * 4];
    float4 o;
    o.x = a.x + b.x + c.x + d.x + bias.x;
    o.y = a.y + b.y + c.y + d.y + bias.y;
    o.z = a.z + b.z + c.z + d.z + bias.z;
    o.w = a.w + b.w + c.w + d.w + bias.w;
    *(float4*)&g_dbc[off] = o;
    if (j4 < 16) {
        __half* hp = &g_dr_h[(size_t)row * RK + j4 * 4];
        *(__half2*)(hp)     = __floats2half2_rn(o.x, o.y);
        *(__half2*)(hp + 2) = __floats2half2_rn(o.z, o.w);
    }
    (void)p0;
}

// ---------------------------------------------------------------------------
// Selective scan fused with D-term and silu(gate); output fp16.
// ---------------------------------------------------------------------------
static constexpr int SCE = 64;
static constexpr int STC = 32;

__global__ __launch_bounds__(256) void scan_kernel(const float* __restrict__ D) {
    __shared__ float s_d[STC][SCE];
    __shared__ float s_u[STC][SCE];
    __shared__ float s_g[STC][SCE];
    __shared__ float s_y[STC][SCE];
    __shared__ float s_bc[STC][32];

    int b  = blockIdx.y;
    int e0 = blockIdx.x * SCE;
    int tid = threadIdx.x;
    int c = tid >> 2;
    int q = tid & 3;
    int e = e0 + c;

    float4 a2 = *(const float4*)&g_A2[e * NS + q * 4];
    float dterm = D[e];
    float h0 = 0.f, h1 = 0.f, h2 = 0.f, h3 = 0.f;

    for (int t0 = 0; t0 < SEQ; t0 += STC) {
        for (int i = tid; i < STC * SCE; i += 256) {
            int tt = i / SCE, ee = i % SCE;
            size_t row = (size_t)(b * SEQ + t0 + tt);
            s_d[tt][ee] = g_delta[row * E + e0 + ee];
            s_u[tt][ee] = g_act[row * (2 * E) + e0 + ee];
            s_g[tt][ee] = g_act[row * (2 * E) + E + e0 + ee];
        }
        for (int i = tid; i < STC * 32; i += 256) {
            int tt = i >> 5, nn = i & 31;
            s_bc[tt][nn] = g_dbc[(size_t)(b * SEQ + t0 + tt) * CATN + 64 + nn];
        }
        __syncthreads();

#pragma unroll 4
        for (int tt = 0; tt < STC; tt++) {
            float d  = s_d[tt][c];
            float uv = s_u[tt][c];
            float du = d * uv;
            float4 bb = *(const float4*)&s_bc[tt][q * 4];
            float4 cc = *(const float4*)&s_bc[tt][16 + q * 4];
            float a0  = ex2f(d * a2.x);
            float a1  = ex2f(d * a2.y);
            float a2v = ex2f(d * a2.z);
            float a3  = ex2f(d * a2.w);
            h0 = fmaf(a0, h0, du * bb.x);
            h1 = fmaf(a1, h1, du * bb.y);
            h2 = fmaf(a2v, h2, du * bb.z);
            h3 = fmaf(a3, h3, du * bb.w);
            float yp = cc.x * h0 + cc.y * h1 + cc.z * h2 + cc.w * h3;
            yp += __shfl_xor_sync(0xffffffffu, yp, 1);
            yp += __shfl_xor_sync(0xffffffffu, yp, 2);
            if (q == 0) s_y[tt][c] = (yp + uv * dterm) * s_g[tt][c];
        }
        __syncthreads();

        for (int i = tid; i < STC * SCE; i += 256) {
            int tt = i / SCE, ee = i % SCE;
            g_yv_h[(size_t)(b * SEQ + t0 + tt) * E + e0 + ee] =
                __float2half(s_y[tt][ee]);
        }
        __syncthreads();
    }
}

// ---------------------------------------------------------------------------
// Launch
// ---------------------------------------------------------------------------
extern "C" void kernel_launch(void* const* d_in, const int* in_sizes, int n_in,
                              void* d_out, int out_size) {
    const float* x       = (const float*)d_in[0];
    const float* ln_g    = (const float*)d_in[1];
    const float* ln_b    = (const float*)d_in[2];
    const float* W_in    = (const float*)d_in[3];
    const float* b_in    = (const float*)d_in[4];
    const float* W_delta = (const float*)d_in[5];
    const float* b_delta = (const float*)d_in[6];
    const float* W_dt    = (const float*)d_in[7];
    const float* b_dt    = (const float*)d_in[8];
    const float* W_B     = (const float*)d_in[9];
    const float* b_B     = (const float*)d_in[10];
    const float* W_C     = (const float*)d_in[11];
    const float* b_C     = (const float*)d_in[12];
    const float* A_log   = (const float*)d_in[13];
    const float* Dp      = (const float*)d_in[14];
    const float* W_out   = (const float*)d_in[15];
    const float* b_out   = (const float*)d_in[16];
    float* out = (float*)d_out;

    __half *p_xnh, *p_uh, *p_drh, *p_yvh, *p_wti, *p_wcat, *p_wdt, *p_wto;
    float *p_act, *p_dbcp, *p_delta;
    cudaGetSymbolAddress((void**)&p_xnh,  g_xn_h);
    cudaGetSymbolAddress((void**)&p_act,  g_act);
    cudaGetSymbolAddress((void**)&p_uh,   g_u_h);
    cudaGetSymbolAddress((void**)&p_dbcp, g_dbc_part);
    cudaGetSymbolAddress((void**)&p_drh,  g_dr_h);
    cudaGetSymbolAddress((void**)&p_delta,g_delta);
    cudaGetSymbolAddress((void**)&p_yvh,  g_yv_h);
    cudaGetSymbolAddress((void**)&p_wti,  g_wti_h);
    cudaGetSymbolAddress((void**)&p_wcat, g_wcat_h);
    cudaGetSymbolAddress((void**)&p_wdt,  g_wdt_h);
    cudaGetSymbolAddress((void**)&p_wto,  g_wto_h);

    // 1. prep: A2/bcat, Wcat^T, and the three transposed fp16 weights
    prep_small<<<(E * NS + 255) / 256, 256>>>(A_log, b_delta, b_B, b_C);
    wcat_kernel<<<CATN * E / 256, 256>>>(W_delta, W_B, W_C);
    trc_kernel<<<dim3(2 * E / 32, H / 32), dim3(32, 8)>>>(W_in, p_wti, H, 2 * E);
    trc_kernel<<<dim3(E / 32, RK / 32), dim3(32, 8)>>>(W_dt, p_wdt, RK, E);
    trc_kernel<<<dim3(H / 32, E / 32), dim3(32, 8)>>>(W_out, p_wto, E, H);

    // 2. layernorm -> fp16
    ln_kernel<<<ROWS, 256>>>(x, ln_g, ln_b);

    // 3. in-proj + silu: act fp32 [8192,4096], u fp16 [8192,2048]
    gemm_f16<1><<<dim3(2 * E / 128, ROWS / 128, 1), 256>>>(
        p_xnh, p_wti, b_in, nullptr, p_act, p_uh, H, H, H, 2 * E, 0);

    // 4. dr|B|C projection, split-K=4 -> partials, then reduce
    gemm_f16<0><<<dim3(1, ROWS / 128, 4), 256>>>(
        p_uh, p_wcat, nullptr, nullptr, p_dbcp, nullptr,
        E / 4, E, E, CATN, (size_t)ROWS * CATN);
    reduce_dbc<<<ROWS * CATN / 4 / 256, 256>>>();

    // 5. delta: softplus(dr @ W_dt + b_dt)  [8192,2048]
    gemm_f16<2><<<dim3(E / 128, ROWS / 128, 1), 256>>>(
        p_drh, p_wdt, b_dt, nullptr, p_delta, nullptr, RK, RK, RK, E, 0);

    // 6. selective scan -> yv fp16
    scan_kernel<<<dim3(E / SCE, BSZ), 256>>>(Dp);

    // 7. out-proj + bias + residual
    gemm_f16<3><<<dim3(H / 128, ROWS / 128, 1), 256>>>(
        p_yvh, p_wto, b_out, x, out, nullptr, E, E, E, H, 0);
}

// round 5
// speedup vs baseline: 1.7562x; 1.0259x over previous
#include <cuda_runtime.h>
#include <cuda_fp16.h>
#include <cstdint>
#include <cstddef>

#define DEV_INLINE __device__ __forceinline__

// ---------------------------------------------------------------------------
// Problem constants
// ---------------------------------------------------------------------------
static constexpr int H  = 1024;
static constexpr int E  = 2048;
static constexpr int NS = 16;     // state dim
static constexpr int RK = 64;     // dt_rank
static constexpr int BSZ = 4;
static constexpr int SEQ = 2048;
static constexpr int ROWS = BSZ * SEQ;          // 8192 tokens
static constexpr int CATN = 128;                // 64 (dr) + 16 (B) + 16 (C) + pad

// ---------------------------------------------------------------------------
// Scratch (device globals: allocation-free rule)
// ---------------------------------------------------------------------------
__device__ __half g_xn_h [(size_t)ROWS * H];          // 16 MB  LN out fp16
__device__ __half g_ug_h [(size_t)ROWS * 2 * E];      // 64 MB  silu(u)|silu(gate) fp16
__device__ float  g_dbc_part[4 * (size_t)ROWS * CATN];// 16 MB  split-K partials
__device__ float  g_dbc  [(size_t)ROWS * CATN];       // 4 MB   dr|B|C fp32
__device__ __half g_dr_h [(size_t)ROWS * RK];         // 1 MB   dr fp16
__device__ __half g_delta_h[(size_t)ROWS * E];        // 32 MB  softplus delta fp16
__device__ __half g_yv_h [(size_t)ROWS * E];          // 32 MB  scan out * gate fp16
__device__ float  g_A2   [E * NS];                    // -exp(A_log)*log2(e)
__device__ float  g_bcat [CATN];
__device__ __half g_wti_h [(size_t)(2 * E) * H];      // W_in^T  [4096][1024] fp16
__device__ __half g_wcat_h[(size_t)CATN * E];         // Wcat^T  [128][2048]  fp16
__device__ __half g_wdt_h [(size_t)E * RK];           // W_dt^T  [2048][64]   fp16
__device__ __half g_wto_h [(size_t)H * E];            // W_out^T [1024][2048] fp16

// ---------------------------------------------------------------------------
// Helpers
// ---------------------------------------------------------------------------
DEV_INLINE uint32_t smem_u32(const void* p) {
    uint32_t a;
    asm("{ .reg .u64 t; cvta.to.shared.u64 t, %1; cvt.u32.u64 %0, t; }"
        : "=r"(a) : "l"(p));
    return a;
}
DEV_INLINE uint32_t sw64(uint32_t off) { return off ^ ((off >> 3) & 0x70); }

DEV_INLINE void cp16(uint32_t dst, const void* src) {
    asm volatile("cp.async.cg.shared.global [%0], [%1], 16;" :: "r"(dst), "l"(src));
}
DEV_INLINE void ldsm4(uint32_t& r0, uint32_t& r1, uint32_t& r2, uint32_t& r3,
                      uint32_t a) {
    asm volatile("ldmatrix.sync.aligned.m8n8.x4.shared.b16 {%0,%1,%2,%3}, [%4];"
                 : "=r"(r0), "=r"(r1), "=r"(r2), "=r"(r3) : "r"(a));
}
DEV_INLINE void mma16816(float c[4], const uint32_t a[4], const uint32_t b[2]) {
    asm volatile(
        "mma.sync.aligned.m16n8k16.row.col.f32.f16.f16.f32 "
        "{%0,%1,%2,%3}, {%4,%5,%6,%7}, {%8,%9}, {%0,%1,%2,%3};"
        : "+f"(c[0]), "+f"(c[1]), "+f"(c[2]), "+f"(c[3])
        : "r"(a[0]), "r"(a[1]), "r"(a[2]), "r"(a[3]), "r"(b[0]), "r"(b[1]));
}

DEV_INLINE float ex2f(float x) {
    float y; asm("ex2.approx.ftz.f32 %0, %1;" : "=f"(y) : "f"(x)); return y;
}
DEV_INLINE float siluf(float v)     { return v / (1.f + __expf(-v)); }
DEV_INLINE float softplusf(float v) { return v > 20.f ? v : log1pf(__expf(v)); }

// ---------------------------------------------------------------------------
// Prep kernels
// ---------------------------------------------------------------------------
__global__ void prep_small(const float* __restrict__ A_log,
                           const float* __restrict__ b_delta,
                           const float* __restrict__ b_B,
                           const float* __restrict__ b_C) {
    int i = blockIdx.x * blockDim.x + threadIdx.x;
    if (i < E * NS) g_A2[i] = -__expf(A_log[i]) * 1.4426950408889634f;
    if (i < CATN) {
        float v = 0.f;
        if (i < 64)      v = b_delta[i];
        else if (i < 80) v = b_B[i - 64];
        else if (i < 96) v = b_C[i - 80];
        g_bcat[i] = v;
    }
}

// Wcat^T [128][2048] fp16 directly from W_delta/W_B/W_C
__global__ void wcat_kernel(const float* __restrict__ W_delta,
                            const float* __restrict__ W_B,
                            const float* __restrict__ W_C) {
    int i = blockIdx.x * blockDim.x + threadIdx.x;   // over CATN*E
    int n = i >> 11, k = i & 2047;
    float v = 0.f;
    if (n < 64)      v = W_delta[k * 64 + n];
    else if (n < 80) v = W_B[k * 16 + (n - 64)];
    else if (n < 96) v = W_C[k * 16 + (n - 80)];
    g_wcat_h[i] = __float2half(v);
}

// transpose + convert: in fp32 [R][C] -> out fp16 [C][R]
__global__ void trc_kernel(const float* __restrict__ in, __half* __restrict__ out,
                           int R, int C) {
    __shared__ float t[32][33];
    int bx = blockIdx.x * 32, by = blockIdx.y * 32;   // bx over C, by over R
    int x = bx + threadIdx.x;
#pragma unroll
    for (int i = 0; i < 32; i += 8)
        t[threadIdx.y + i][threadIdx.x] = in[(size_t)(by + threadIdx.y + i) * C + x];
    __syncthreads();
    int ox = by + threadIdx.x;
#pragma unroll
    for (int i = 0; i < 32; i += 8)
        out[(size_t)(bx + threadIdx.y + i) * R + ox] =
            __float2half(t[threadIdx.x][threadIdx.y + i]);
}

// ---------------------------------------------------------------------------
// LayerNorm -> fp16
// ---------------------------------------------------------------------------
__global__ __launch_bounds__(256) void ln_kernel(const float* __restrict__ x,
                                                 const float* __restrict__ g,
                                                 const float* __restrict__ b) {
    int row = blockIdx.x, tid = threadIdx.x;
    float4 v = ((const float4*)(x + (size_t)row * H))[tid];
    float s  = v.x + v.y + v.z + v.w;
    float ss = v.x * v.x + v.y * v.y + v.z * v.z + v.w * v.w;
#pragma unroll
    for (int o = 16; o; o >>= 1) {
        s  += __shfl_xor_sync(0xffffffffu, s, o);
        ss += __shfl_xor_sync(0xffffffffu, ss, o);
    }
    __shared__ float rs[8], rss[8];
    if ((tid & 31) == 0) { rs[tid >> 5] = s; rss[tid >> 5] = ss; }
    __syncthreads();
    s = 0.f; ss = 0.f;
#pragma unroll
    for (int i = 0; i < 8; i++) { s += rs[i]; ss += rss[i]; }
    float mean = s * (1.f / H);
    float var  = ss * (1.f / H) - mean * mean;
    float rstd = rsqrtf(var + 1e-5f);
    float4 gg = ((const float4*)g)[tid];
    float4 bb = ((const float4*)b)[tid];
    float o0 = (v.x - mean) * rstd * gg.x + bb.x;
    float o1 = (v.y - mean) * rstd * gg.y + bb.y;
    float o2 = (v.z - mean) * rstd * gg.z + bb.z;
    float o3 = (v.w - mean) * rstd * gg.w + bb.w;
    __half* op = g_xn_h + (size_t)row * H + 4 * tid;
    *(__half2*)(op)     = __floats2half2_rn(o0, o1);
    *(__half2*)(op + 2) = __floats2half2_rn(o2, o3);
}

// ---------------------------------------------------------------------------
// fp16 mma.sync GEMM, 128x128x32 tiles, 3-stage cp.async, ldmatrix.
// C = epi(A[M,K] @ Bt[N,K]^T + bias)
//   A fp16 row-major (lda), Bt fp16 [N][K] row-major (ldb)
// EPI: 0 raw fp32 (split-K partial), 1 silu -> fp16 Ch, 2 softplus -> fp16 Ch,
//      3 bias + extra (residual) -> fp32 Cf
// ---------------------------------------------------------------------------
template <int EPI>
__global__ void __launch_bounds__(256)
gemm_f16(const __half* __restrict__ A, const __half* __restrict__ Bt,
         const float* __restrict__ bias, const float* __restrict__ extra,
         float* __restrict__ Cf, __half* __restrict__ Ch,
         int K, int lda, int ldb, int ldc, size_t partStride) {
    __shared__ char smem[49152];          // 3 stages x (8KB A + 8KB B)
    uint32_t sb = smem_u32(smem);

    int tid = threadIdx.x, wid = tid >> 5, lane = tid & 31;
    int wm = wid >> 2, wn = wid & 3;       // 2 x 4 warps
    int bm = blockIdx.y, bn = blockIdx.x;
    int kbase = blockIdx.z * K;
    Cf += (size_t)blockIdx.z * partStride;

    // loader: thread -> rows {lr, lr+64}, 16B chunk lc
    int lr = tid >> 2, lc = tid & 3;
    const __half* Ag = A + (size_t)(bm * 128 + lr) * lda + kbase + lc * 8;
    const __half* Bg = Bt + (size_t)(bn * 128 + lr) * ldb + kbase + lc * 8;
    uint32_t swl0 = sw64((uint32_t)lr * 64 + lc * 16);
    uint32_t swl1 = sw64((uint32_t)(lr + 64) * 64 + lc * 16);

    int nkt = K / 32;
#define ISSUE(kt, s) do {                                                     \
        const __half* Ak = Ag + (kt) * 32;                                    \
        const __half* Bk = Bg + (kt) * 32;                                    \
        uint32_t base = sb + (s) * 16384;                                     \
        cp16(base + swl0, Ak);                                                \
        cp16(base + swl1, Ak + (size_t)64 * lda);                             \
        cp16(base + 8192 + swl0, Bk);                                         \
        cp16(base + 8192 + swl1, Bk + (size_t)64 * ldb);                      \
    } while (0)

    if (0 < nkt) ISSUE(0, 0);
    asm volatile("cp.async.commit_group;" ::: "memory");
    if (1 < nkt) ISSUE(1, 1);
    asm volatile("cp.async.commit_group;" ::: "memory");

    float acc[4][4][4];
#pragma unroll
    for (int mi = 0; mi < 4; mi++)
#pragma unroll
        for (int ni = 0; ni < 4; ni++)
#pragma unroll
            for (int j = 0; j < 4; j++) acc[mi][ni][j] = 0.f;

    int within = lane & 7, mat = lane >> 3;

    for (int kt = 0; kt < nkt; kt++) {
        asm volatile("cp.async.wait_group 1;" ::: "memory");
        __syncthreads();
        int pre = kt + 2;
        if (pre < nkt) ISSUE(pre, pre % 3);
        asm volatile("cp.async.commit_group;" ::: "memory");

        uint32_t sA = sb + (kt % 3) * 16384;
        uint32_t sB = sA + 8192;
#pragma unroll
        for (int kk = 0; kk < 2; kk++) {
            uint32_t af[4][4], bf[4][2];
#pragma unroll
            for (int mi = 0; mi < 4; mi++) {
                int ra = wm * 64 + mi * 16;
                int row = ra + within + ((mat & 1) << 3);
                int ch  = 2 * kk + (mat >> 1);
                uint32_t ad = sA + sw64((uint32_t)row * 64 + ch * 16);
                ldsm4(af[mi][0], af[mi][1], af[mi][2], af[mi][3], ad);
            }
#pragma unroll
            for (int np = 0; np < 2; np++) {
                int nb = wn * 32 + np * 16;
                int n  = nb + within + ((mat >> 1) << 3);
                int ch = 2 * kk + (mat & 1);
                uint32_t bd = sB + sw64((uint32_t)n * 64 + ch * 16);
                uint32_t r0, r1, r2, r3;
                ldsm4(r0, r1, r2, r3, bd);
                bf[2 * np][0] = r0; bf[2 * np][1] = r1;
                bf[2 * np + 1][0] = r2; bf[2 * np + 1][1] = r3;
            }
#pragma unroll
            for (int mi = 0; mi < 4; mi++)
#pragma unroll
                for (int ni = 0; ni < 4; ni++)
                    mma16816(acc[mi][ni], af[mi], bf[ni]);
        }
        __syncthreads();
    }
#undef ISSUE

    // epilogue
#pragma unroll
    for (int mi = 0; mi < 4; mi++) {
#pragma unroll
        for (int ni = 0; ni < 4; ni++) {
            int r  = bm * 128 + wm * 64 + mi * 16 + (lane >> 2);
            int c0 = bn * 128 + wn * 32 + ni * 8 + (lane & 3) * 2;
            float v0 = acc[mi][ni][0], v1 = acc[mi][ni][1];
            float v2 = acc[mi][ni][2], v3 = acc[mi][ni][3];
            if (EPI != 0) {
                float b0 = bias[c0], b1 = bias[c0 + 1];
                v0 += b0; v1 += b1; v2 += b0; v3 += b1;
            }
            if (EPI == 1) {
                v0 = siluf(v0); v1 = siluf(v1); v2 = siluf(v2); v3 = siluf(v3);
            } else if (EPI == 2) {
                v0 = softplusf(v0); v1 = softplusf(v1);
                v2 = softplusf(v2); v3 = softplusf(v3);
            } else if (EPI == 3) {
                v0 += extra[(size_t)r * ldc + c0];
                v1 += extra[(size_t)r * ldc + c0 + 1];
                v2 += extra[(size_t)(r + 8) * ldc + c0];
                v3 += extra[(size_t)(r + 8) * ldc + c0 + 1];
            }
            if (EPI == 1 || EPI == 2) {
                *(__half2*)&Ch[(size_t)r * ldc + c0]       = __floats2half2_rn(v0, v1);
                *(__half2*)&Ch[(size_t)(r + 8) * ldc + c0] = __floats2half2_rn(v2, v3);
            } else {
                *(float2*)&Cf[(size_t)r * ldc + c0]       = make_float2(v0, v1);
                *(float2*)&Cf[(size_t)(r + 8) * ldc + c0] = make_float2(v2, v3);
            }
        }
    }
}

// ---------------------------------------------------------------------------
// Reduce split-K partials + bias -> dbc fp32, dr fp16
// ---------------------------------------------------------------------------
__global__ void reduce_dbc() {
    int i = blockIdx.x * blockDim.x + threadIdx.x;   // over ROWS*CATN/4
    int row = i >> 5, j4 = i & 31;
    size_t off = (size_t)row * CATN + j4 * 4;
    size_t stride4 = (size_t)ROWS * CATN / 4;
    float4 a = ((const float4*)g_dbc_part)[off / 4];
    float4 b = ((const float4*)g_dbc_part)[off / 4 + stride4];
    float4 c = ((const float4*)g_dbc_part)[off / 4 + 2 * stride4];
    float4 d = ((const float4*)g_dbc_part)[off / 4 + 3 * stride4];
    float4 bias = *(const float4*)&g_bcat[j4 * 4];
    float4 o;
    o.x = a.x + b.x + c.x + d.x + bias.x;
    o.y = a.y + b.y + c.y + d.y + bias.y;
    o.z = a.z + b.z + c.z + d.z + bias.z;
    o.w = a.w + b.w + c.w + d.w + bias.w;
    *(float4*)&g_dbc[off] = o;
    if (j4 < 16) {
        __half* hp = &g_dr_h[(size_t)row * RK + j4 * 4];
        *(__half2*)(hp)     = __floats2half2_rn(o.x, o.y);
        *(__half2*)(hp + 2) = __floats2half2_rn(o.z, o.w);
    }
}

// ---------------------------------------------------------------------------
// Selective scan fused with D-term and silu(gate); fp16 in/out.
// CTA: 64 channels x 4 threads (4 states each). grid = (E/64, BSZ).
// ---------------------------------------------------------------------------
static constexpr int SCE = 64;
static constexpr int STC = 32;

__global__ __launch_bounds__(256) void scan_kernel(const float* __restrict__ D) {
    __shared__ float s_d[STC][SCE];
    __shared__ float s_u[STC][SCE];
    __shared__ float s_g[STC][SCE];
    __shared__ float s_y[STC][SCE];
    __shared__ float s_bc[STC][32];

    int b  = blockIdx.y;
    int e0 = blockIdx.x * SCE;
    int tid = threadIdx.x;
    int c = tid >> 2;
    int q = tid & 3;
    int e = e0 + c;

    float4 a2 = *(const float4*)&g_A2[e * NS + q * 4];
    float dterm = D[e];
    float h0 = 0.f, h1 = 0.f, h2 = 0.f, h3 = 0.f;

    for (int t0 = 0; t0 < SEQ; t0 += STC) {
        // stage inputs: half2 loads, fp32 smem
        for (int i = tid; i < STC * (SCE / 2); i += 256) {
            int tt = i / (SCE / 2), e2 = i % (SCE / 2);
            size_t row = (size_t)(b * SEQ + t0 + tt);
            float2 dv = __half22float2(
                *(const __half2*)&g_delta_h[row * E + e0 + 2 * e2]);
            float2 uv = __half22float2(
                *(const __half2*)&g_ug_h[row * (2 * E) + e0 + 2 * e2]);
            float2 gv = __half22float2(
                *(const __half2*)&g_ug_h[row * (2 * E) + E + e0 + 2 * e2]);
            s_d[tt][2 * e2] = dv.x; s_d[tt][2 * e2 + 1] = dv.y;
            s_u[tt][2 * e2] = uv.x; s_u[tt][2 * e2 + 1] = uv.y;
            s_g[tt][2 * e2] = gv.x; s_g[tt][2 * e2 + 1] = gv.y;
        }
        for (int i = tid; i < STC * 32; i += 256) {
            int tt = i >> 5, nn = i & 31;
            s_bc[tt][nn] = g_dbc[(size_t)(b * SEQ + t0 + tt) * CATN + 64 + nn];
        }
        __syncthreads();

#pragma unroll 4
        for (int tt = 0; tt < STC; tt++) {
            float d  = s_d[tt][c];
            float uv = s_u[tt][c];
            float du = d * uv;
            float4 bb = *(const float4*)&s_bc[tt][q * 4];
            float4 cc = *(const float4*)&s_bc[tt][16 + q * 4];
            float a0  = ex2f(d * a2.x);
            float a1  = ex2f(d * a2.y);
            float a2v = ex2f(d * a2.z);
            float a3  = ex2f(d * a2.w);
            h0 = fmaf(a0, h0, du * bb.x);
            h1 = fmaf(a1, h1, du * bb.y);
            h2 = fmaf(a2v, h2, du * bb.z);
            h3 = fmaf(a3, h3, du * bb.w);
            float yp = cc.x * h0 + cc.y * h1 + cc.z * h2 + cc.w * h3;
            yp += __shfl_xor_sync(0xffffffffu, yp, 1);
            yp += __shfl_xor_sync(0xffffffffu, yp, 2);
            if (q == 0) s_y[tt][c] = (yp + uv * dterm) * s_g[tt][c];
        }
        __syncthreads();

        for (int i = tid; i < STC * (SCE / 2); i += 256) {
            int tt = i / (SCE / 2), e2 = i % (SCE / 2);
            *(__half2*)&g_yv_h[(size_t)(b * SEQ + t0 + tt) * E + e0 + 2 * e2] =
                __floats2half2_rn(s_y[tt][2 * e2], s_y[tt][2 * e2 + 1]);
        }
        __syncthreads();
    }
}

// ---------------------------------------------------------------------------
// Launch
// ---------------------------------------------------------------------------
extern "C" void kernel_launch(void* const* d_in, const int* in_sizes, int n_in,
                              void* d_out, int out_size) {
    const float* x       = (const float*)d_in[0];
    const float* ln_g    = (const float*)d_in[1];
    const float* ln_b    = (const float*)d_in[2];
    const float* W_in    = (const float*)d_in[3];
    const float* b_in    = (const float*)d_in[4];
    const float* W_delta = (const float*)d_in[5];
    const float* b_delta = (const float*)d_in[6];
    const float* W_dt    = (const float*)d_in[7];
    const float* b_dt    = (const float*)d_in[8];
    const float* W_B     = (const float*)d_in[9];
    const float* b_B     = (const float*)d_in[10];
    const float* W_C     = (const float*)d_in[11];
    const float* b_C     = (const float*)d_in[12];
    const float* A_log   = (const float*)d_in[13];
    const float* Dp      = (const float*)d_in[14];
    const float* W_out   = (const float*)d_in[15];
    const float* b_out   = (const float*)d_in[16];
    float* out = (float*)d_out;

    __half *p_xnh, *p_ugh, *p_drh, *p_dlth, *p_yvh, *p_wti, *p_wcat, *p_wdt, *p_wto;
    float *p_dbcp;
    cudaGetSymbolAddress((void**)&p_xnh,  g_xn_h);
    cudaGetSymbolAddress((void**)&p_ugh,  g_ug_h);
    cudaGetSymbolAddress((void**)&p_dbcp, g_dbc_part);
    cudaGetSymbolAddress((void**)&p_drh,  g_dr_h);
    cudaGetSymbolAddress((void**)&p_dlth, g_delta_h);
    cudaGetSymbolAddress((void**)&p_yvh,  g_yv_h);
    cudaGetSymbolAddress((void**)&p_wti,  g_wti_h);
    cudaGetSymbolAddress((void**)&p_wcat, g_wcat_h);
    cudaGetSymbolAddress((void**)&p_wdt,  g_wdt_h);
    cudaGetSymbolAddress((void**)&p_wto,  g_wto_h);

    // 1. prep: A2/bcat, Wcat^T, transposed fp16 weights
    prep_small<<<(E * NS + 255) / 256, 256>>>(A_log, b_delta, b_B, b_C);
    wcat_kernel<<<CATN * E / 256, 256>>>(W_delta, W_B, W_C);
    trc_kernel<<<dim3(2 * E / 32, H / 32), dim3(32, 8)>>>(W_in, p_wti, H, 2 * E);
    trc_kernel<<<dim3(E / 32, RK / 32), dim3(32, 8)>>>(W_dt, p_wdt, RK, E);
    trc_kernel<<<dim3(H / 32, E / 32), dim3(32, 8)>>>(W_out, p_wto, E, H);

    // 2. layernorm -> fp16
    ln_kernel<<<ROWS, 256>>>(x, ln_g, ln_b);

    // 3. in-proj + silu -> ug fp16 [8192, 4096]
    gemm_f16<1><<<dim3(2 * E / 128, ROWS / 128, 1), 256>>>(
        p_xnh, p_wti, b_in, nullptr, nullptr, p_ugh, H, H, H, 2 * E, 0);

    // 4. dr|B|C projection, split-K=4 -> partials, then reduce
    gemm_f16<0><<<dim3(1, ROWS / 128, 4), 256>>>(
        p_ugh, p_wcat, nullptr, nullptr, p_dbcp, nullptr,
        E / 4, 2 * E, E, CATN, (size_t)ROWS * CATN);
    reduce_dbc<<<ROWS * CATN / 4 / 256, 256>>>();

    // 5. delta: softplus(dr @ W_dt + b_dt) -> fp16 [8192, 2048]
    gemm_f16<2><<<dim3(E / 128, ROWS / 128, 1), 256>>>(
        p_drh, p_wdt, b_dt, nullptr, nullptr, p_dlth, RK, RK, RK, E, 0);

    // 6. selective scan -> yv fp16
    scan_kernel<<<dim3(E / SCE, BSZ), 256>>>(Dp);

    // 7. out-proj + bias + residual -> fp32 out
    gemm_f16<3><<<dim3(H / 128, ROWS / 128, 1), 256>>>(
        p_yvh, p_wto, b_out, x, out, nullptr, E, E, E, H, 0);
}